// round 12
// baseline (speedup 1.0000x reference)
#include <cuda_runtime.h>
#include <cstdint>

#define PI  3.14159265358979323846f
#define PIH 1.57079632679489662f
#define IR2 0.70710678118654752f

// 16 MB scratch between passes (fits in L2)
__device__ float4 g_scr[1 << 20];

__device__ __forceinline__ float sin_ap(float x){ float y; asm("sin.approx.f32 %0, %1;" : "=f"(y) : "f"(x)); return y; }
__device__ __forceinline__ float sqrt_ap(float x){ float y; asm("sqrt.approx.f32 %0, %1;" : "=f"(y) : "f"(x)); return y; }
// conflict-free for float4 tiles at the strided patterns used
__device__ __forceinline__ int swz(int r){ return r ^ ((r >> 4) & 3) ^ (((r >> 5) & 3) << 2); }

// squared-magnitude butterfly; clamp product (tiny negatives from rounding)
__device__ __forceinline__ void bfly(float& Se, float& So, float c){
    float r  = sqrt_ap(fmaxf(Se * So, 0.f));
    float T  = c * r;
    float Sp = Se + So;
    Se = fmaf( 2.f, T, Sp);
    So = fmaf(-2.f, T, Sp);
}

struct Coef { float c1, cH, msH, q0, q1, q2, q3; };

// radix-8 twiddles from quarter-angle (s4, c4) = (sin h4, cos h4)
__device__ __forceinline__ Coef mkcoef_sc(float s4, float c4){
    Coef k;
    float sH = 2.f * s4 * c4;
    float cH = fmaf(-2.f * s4, s4, 1.f);
    k.c1  = fmaf(2.f * cH, cH, -1.f);
    k.cH  = cH;  k.msH = -sH;
    k.q0  = c4;
    k.q1  = (c4 - s4) * IR2;
    k.q2  = -s4;
    k.q3  = -(c4 + s4) * IR2;
    return k;
}
__device__ __forceinline__ Coef mkcoef(float h4){
    return mkcoef_sc(sin_ap(h4), sin_ap(PIH - h4));
}

// Pass A: stages pair ascending bits
__device__ __forceinline__ void r8A_apply(float* v, const Coef& k){
    bfly(v[0],v[1],k.c1);  bfly(v[2],v[3],k.c1);  bfly(v[4],v[5],k.c1);  bfly(v[6],v[7],k.c1);
    bfly(v[0],v[2],k.cH);  bfly(v[1],v[3],k.msH); bfly(v[4],v[6],k.cH);  bfly(v[5],v[7],k.msH);
    bfly(v[0],v[4],k.q0);  bfly(v[1],v[5],k.q1);  bfly(v[2],v[6],k.q2);  bfly(v[3],v[7],k.q3);
}
// Pass B: stages pair descending bits
__device__ __forceinline__ void r8B_apply(float* v, const Coef& k){
    bfly(v[0],v[4],k.c1);  bfly(v[1],v[5],k.c1);  bfly(v[2],v[6],k.c1);  bfly(v[3],v[7],k.c1);
    bfly(v[0],v[2],k.cH);  bfly(v[1],v[3],k.cH);  bfly(v[4],v[6],k.msH); bfly(v[5],v[7],k.msH);
    bfly(v[0],v[1],k.q0);  bfly(v[2],v[3],k.q2);  bfly(v[4],v[5],k.q1);  bfly(v[6],v[7],k.q3);
}

template<int B>
__device__ __forceinline__ void r8A(float4* tile, int t){
    const int   j0   = t & ((1 << B) - 1);
    const int   base = ((t >> B) << (B + 3)) | j0;
    const float h4   = (float)j0 * (PI / (float)(4 << B));
    Coef k = mkcoef(h4);
    int idx[8]; float4 v[8]; float a[8];
    #pragma unroll
    for (int n = 0; n < 8; n++){ idx[n] = swz(base + (n << B)); v[n] = tile[idx[n]]; }
    #pragma unroll
    for (int n = 0; n < 8; n++) a[n] = v[n].x;
    r8A_apply(a, k);
    #pragma unroll
    for (int n = 0; n < 8; n++){ v[n].x = a[n]; a[n] = v[n].y; }
    r8A_apply(a, k);
    #pragma unroll
    for (int n = 0; n < 8; n++){ v[n].y = a[n]; a[n] = v[n].z; }
    r8A_apply(a, k);
    #pragma unroll
    for (int n = 0; n < 8; n++){ v[n].z = a[n]; a[n] = v[n].w; }
    r8A_apply(a, k);
    #pragma unroll
    for (int n = 0; n < 8; n++){ v[n].w = a[n]; tile[idx[n]] = v[n]; }
}

// pass-B radix-8 on registers; per-lane quarter-angle advanced by FMA rotation
__device__ __forceinline__ void r8B_regs_rot(float4* v, float s4, float c4,
                                             float ss, float cc){
    float a[8];
    {   Coef k = mkcoef_sc(s4, c4);
        #pragma unroll
        for (int n = 0; n < 8; n++) a[n] = v[n].x;
        r8B_apply(a, k);
        #pragma unroll
        for (int n = 0; n < 8; n++) v[n].x = a[n];
    }
    float s1 = fmaf(c4, ss, s4 * cc), c1 = fmaf(-s4, ss, c4 * cc);
    {   Coef k = mkcoef_sc(s1, c1);
        #pragma unroll
        for (int n = 0; n < 8; n++) a[n] = v[n].y;
        r8B_apply(a, k);
        #pragma unroll
        for (int n = 0; n < 8; n++) v[n].y = a[n];
    }
    float s2 = fmaf(c1, ss, s1 * cc), c2 = fmaf(-s1, ss, c1 * cc);
    {   Coef k = mkcoef_sc(s2, c2);
        #pragma unroll
        for (int n = 0; n < 8; n++) a[n] = v[n].z;
        r8B_apply(a, k);
        #pragma unroll
        for (int n = 0; n < 8; n++) v[n].z = a[n];
    }
    float s3 = fmaf(c2, ss, s2 * cc), c3 = fmaf(-s2, ss, c2 * cc);
    {   Coef k = mkcoef_sc(s3, c3);
        #pragma unroll
        for (int n = 0; n < 8; n++) a[n] = v[n].w;
        r8B_apply(a, k);
        #pragma unroll
        for (int n = 0; n < 8; n++) v[n].w = a[n];
    }
}

template<int B>
__device__ __forceinline__ void r8B(float4* tile, int t, int R0){
    const int   mtop = (1 << (8 - B)) - 1;
    const int   base = ((t >> B) << (B + 3)) | (t & ((1 << B) - 1));
    const float sc   = PI / (float)(1 << (21 - B));
    const float cc   = 1.f - 0.5f * sc * sc;
    int   rl = (int)(__brev((unsigned)base) >> 21);
    int   jb = ((rl & mtop) << 11) + R0;
    float h0 = (float)jb * sc;
    int idx[8]; float4 v[8];
    #pragma unroll
    for (int n = 0; n < 8; n++){ idx[n] = swz(base + (n << B)); v[n] = tile[idx[n]]; }
    float s0 = sin_ap(h0), c0 = sin_ap(PIH - h0);
    r8B_regs_rot(v, s0, c0, sc, cc);
    #pragma unroll
    for (int n = 0; n < 8; n++) tile[idx[n]] = v[n];
}

// ================= Pass A: stages 1..11 =================
__global__ void __launch_bounds__(256) fftA(const float4* __restrict__ x4){
    __shared__ float4 tile[2048];
    const int t   = threadIdx.x;
    const int lb4 = blockIdx.x;
    const int w   = t >> 5, ln = t & 31;

    // fused load + closed-form stages (1,2)
    #pragma unroll
    for (int m = 0; m < 2; m++){
        int g = (w << 6) | ln | (m << 5);
        int b = g << 2;
        float4 e0 = x4[(((int)(__brev((unsigned)(b + 0)) >> 21)) << 9) + lb4];
        float4 e1 = x4[(((int)(__brev((unsigned)(b + 1)) >> 21)) << 9) + lb4];
        float4 e2 = x4[(((int)(__brev((unsigned)(b + 2)) >> 21)) << 9) + lb4];
        float4 e3 = x4[(((int)(__brev((unsigned)(b + 3)) >> 21)) << 9) + lb4];
        float4 w0, w1, w2;
#define G12(L) { \
        float A  = fabsf(e0.L + e1.L), Bv = fabsf(e2.L + e3.L); \
        float d1 = e0.L - e1.L,        d2 = e2.L - e3.L;        \
        float s  = A + Bv,             q  = A - Bv;             \
        w0.L = s * s; w2.L = q * q; w1.L = fmaf(d1, d1, d2 * d2); }
        G12(x) G12(y) G12(z) G12(w)
#undef G12
        tile[swz(b)] = w0; tile[swz(b + 1)] = w1; tile[swz(b + 2)] = w2; tile[swz(b + 3)] = w1;
    }
    __syncwarp();

    r8A<2>(tile, t); __syncwarp();      // stages 3,4,5 (warp-local rows)
    r8A<5>(tile, t); __syncthreads();   // stages 6,7,8
    r8A<8>(tile, t); __syncthreads();   // stages 9,10,11

    // vectorized transpose-store to scratch (pass-B layout):
    // thread handles G-groups via conflict-free map; 4xLDS.128 -> reg 4x4 transpose -> 4xSTG.128
    {
        // G bits: (t0, t3, t1, t2, t4..t7, m) -> LDS bank residue bijective per 8-lane phase
        int Gb = (t & 1) | (((t >> 3) & 1) << 1) | (((t >> 1) & 1) << 2)
               | (((t >> 2) & 1) << 3) | ((t >> 4) << 4);
        #pragma unroll
        for (int m = 0; m < 2; m++){
            int G = Gb | (m << 8);
            float4 r0 = tile[swz((G << 2) | 0)];
            float4 r1 = tile[swz((G << 2) | 1)];
            float4 r2 = tile[swz((G << 2) | 2)];
            float4 r3 = tile[swz((G << 2) | 3)];
            float4* dst = g_scr + (G << 11) + (lb4 << 2);
            dst[0] = make_float4(r0.x, r1.x, r2.x, r3.x);
            dst[1] = make_float4(r0.y, r1.y, r2.y, r3.y);
            dst[2] = make_float4(r0.z, r1.z, r2.z, r3.z);
            dst[3] = make_float4(r0.w, r1.w, r2.w, r3.w);
        }
    }
}

// ================= Pass B: stages 12..22 + sqrt + bit-reversed store =================
__global__ void __launch_bounds__(256) fftB(float4* __restrict__ out4){
    __shared__ float4 tile[2048];
    const int t  = threadIdx.x;
    const int g  = blockIdx.x;
    const int R0 = g << 2;
    const int w  = t >> 5, ln = t & 31;

    // round 1 (stages 12,13,14): register-forwarded load (rows t + 256n)
    {
        const float sc = PI / (float)(1 << 13);
        const float cc = 1.f - 0.5f * sc * sc;
        float h0 = (float)R0 * sc;       // jb = R0
        float4 v[8];
        const float4* src = g_scr + ((long)g << 11) + t;
        #pragma unroll
        for (int n = 0; n < 8; n++) v[n] = src[n << 8];
        float s0 = sin_ap(h0), c0 = sin_ap(PIH - h0);
        r8B_regs_rot(v, s0, c0, sc, cc);
        #pragma unroll
        for (int n = 0; n < 8; n++) tile[swz(t + (n << 8))] = v[n];
    }
    __syncthreads();

    r8B<5>(tile, t, R0); __syncwarp();   // stages 15,16,17 (warp-local)
    r8B<2>(tile, t, R0); __syncwarp();   // stages 18,19,20 (warp-local)

    // final radix-4 (stages 21,22) + sqrt + bit-reversed scatter
    {
        const float hs = PI / (float)(1 << 21);
        #pragma unroll
        for (int m = 0; m < 2; m++){
            int gb   = (w << 6) | ln | (m << 5);
            int base = gb << 2;
            int i00 = swz(base), i01 = swz(base + 1), i10 = swz(base + 2), i11 = swz(base + 3);
            int rl = (int)(__brev((unsigned)base) >> 21);
            int jb = ((rl & 511) << 11) + R0;
            float h0 = (float)jb * hs;
            float4 v00 = tile[i00], v01 = tile[i01], v10 = tile[i10], v11 = tile[i11];
            float sh = sin_ap(h0), ch = sin_ap(PIH - h0);
#define RLF(L) { \
            float c2 = fmaf(-2.f * sh, sh, 1.f); float msh = -sh; \
            bfly(v00.L, v10.L, c2); bfly(v01.L, v11.L, c2); \
            bfly(v00.L, v01.L, ch); bfly(v10.L, v11.L, msh); }
#define ROT()  { float sn = fmaf(ch, hs, sh); ch = fmaf(-sh, hs, ch); sh = sn; }
            RLF(x) ROT()
            RLF(y) ROT()
            RLF(z) ROT()
            RLF(w)
#undef ROT
#undef RLF
#define SQ4(v) make_float4(sqrt_ap(fmaxf(v.x,0.f)), sqrt_ap(fmaxf(v.y,0.f)), \
                           sqrt_ap(fmaxf(v.z,0.f)), sqrt_ap(fmaxf(v.w,0.f)))
            out4[(((int)(__brev((unsigned)(base + 0)) >> 21)) << 9) + g] = SQ4(v00);
            out4[(((int)(__brev((unsigned)(base + 1)) >> 21)) << 9) + g] = SQ4(v01);
            out4[(((int)(__brev((unsigned)(base + 2)) >> 21)) << 9) + g] = SQ4(v10);
            out4[(((int)(__brev((unsigned)(base + 3)) >> 21)) << 9) + g] = SQ4(v11);
#undef SQ4
        }
    }
}

extern "C" void kernel_launch(void* const* d_in, const int* in_sizes, int n_in,
                              void* d_out, int out_size) {
    const float4* x4 = (const float4*)d_in[0];
    fftA<<<512, 256>>>(x4);
    fftB<<<512, 256>>>((float4*)d_out);
}

// round 13
// speedup vs baseline: 1.0476x; 1.0476x over previous
#include <cuda_runtime.h>
#include <cstdint>

#define PI  3.14159265358979323846f
#define PIH 1.57079632679489662f
#define IR2 0.70710678118654752f

// 16 MB scratch between passes (fits in L2)
__device__ float4 g_scr[1 << 20];

__device__ __forceinline__ float sin_ap(float x){ float y; asm("sin.approx.f32 %0, %1;" : "=f"(y) : "f"(x)); return y; }
__device__ __forceinline__ float sqrt_ap(float x){ float y; asm("sqrt.approx.f32 %0, %1;" : "=f"(y) : "f"(x)); return y; }
// conflict-free for float4 tiles at the strided patterns used
__device__ __forceinline__ int swz(int r){ return r ^ ((r >> 4) & 3) ^ (((r >> 5) & 3) << 2); }

// squared-magnitude butterfly; clamp product (tiny negatives from rounding)
__device__ __forceinline__ void bfly(float& Se, float& So, float c){
    float r  = sqrt_ap(fmaxf(Se * So, 0.f));
    float T  = c * r;
    float Sp = Se + So;
    Se = fmaf( 2.f, T, Sp);
    So = fmaf(-2.f, T, Sp);
}

struct Coef { float c1, cH, msH, q0, q1, q2, q3; };

// radix-8 twiddles from quarter-angle (s4, c4) = (sin h4, cos h4)
__device__ __forceinline__ Coef mkcoef_sc(float s4, float c4){
    Coef k;
    float sH = 2.f * s4 * c4;
    float cH = fmaf(-2.f * s4, s4, 1.f);
    k.c1  = fmaf(2.f * cH, cH, -1.f);
    k.cH  = cH;  k.msH = -sH;
    k.q0  = c4;
    k.q1  = (c4 - s4) * IR2;
    k.q2  = -s4;
    k.q3  = -(c4 + s4) * IR2;
    return k;
}
__device__ __forceinline__ Coef mkcoef(float h4){
    return mkcoef_sc(sin_ap(h4), sin_ap(PIH - h4));
}

// Pass A: stages pair ascending bits
__device__ __forceinline__ void r8A_apply(float* v, const Coef& k){
    bfly(v[0],v[1],k.c1);  bfly(v[2],v[3],k.c1);  bfly(v[4],v[5],k.c1);  bfly(v[6],v[7],k.c1);
    bfly(v[0],v[2],k.cH);  bfly(v[1],v[3],k.msH); bfly(v[4],v[6],k.cH);  bfly(v[5],v[7],k.msH);
    bfly(v[0],v[4],k.q0);  bfly(v[1],v[5],k.q1);  bfly(v[2],v[6],k.q2);  bfly(v[3],v[7],k.q3);
}
// Pass B: stages pair descending bits
__device__ __forceinline__ void r8B_apply(float* v, const Coef& k){
    bfly(v[0],v[4],k.c1);  bfly(v[1],v[5],k.c1);  bfly(v[2],v[6],k.c1);  bfly(v[3],v[7],k.c1);
    bfly(v[0],v[2],k.cH);  bfly(v[1],v[3],k.cH);  bfly(v[4],v[6],k.msH); bfly(v[5],v[7],k.msH);
    bfly(v[0],v[1],k.q0);  bfly(v[2],v[3],k.q2);  bfly(v[4],v[5],k.q1);  bfly(v[6],v[7],k.q3);
}

template<int B>
__device__ __forceinline__ void r8A(float4* tile, int t){
    const int   j0   = t & ((1 << B) - 1);
    const int   base = ((t >> B) << (B + 3)) | j0;
    const float h4   = (float)j0 * (PI / (float)(4 << B));
    Coef k = mkcoef(h4);
    int idx[8]; float4 v[8]; float a[8];
    #pragma unroll
    for (int n = 0; n < 8; n++){ idx[n] = swz(base + (n << B)); v[n] = tile[idx[n]]; }
    #pragma unroll
    for (int n = 0; n < 8; n++) a[n] = v[n].x;
    r8A_apply(a, k);
    #pragma unroll
    for (int n = 0; n < 8; n++){ v[n].x = a[n]; a[n] = v[n].y; }
    r8A_apply(a, k);
    #pragma unroll
    for (int n = 0; n < 8; n++){ v[n].y = a[n]; a[n] = v[n].z; }
    r8A_apply(a, k);
    #pragma unroll
    for (int n = 0; n < 8; n++){ v[n].z = a[n]; a[n] = v[n].w; }
    r8A_apply(a, k);
    #pragma unroll
    for (int n = 0; n < 8; n++){ v[n].w = a[n]; tile[idx[n]] = v[n]; }
}

// pass-B radix-8 on registers; per-lane quarter-angle advanced by FMA rotation
__device__ __forceinline__ void r8B_regs_rot(float4* v, float s4, float c4,
                                             float ss, float cc){
    float a[8];
    {   Coef k = mkcoef_sc(s4, c4);
        #pragma unroll
        for (int n = 0; n < 8; n++) a[n] = v[n].x;
        r8B_apply(a, k);
        #pragma unroll
        for (int n = 0; n < 8; n++) v[n].x = a[n];
    }
    float s1 = fmaf(c4, ss, s4 * cc), c1 = fmaf(-s4, ss, c4 * cc);
    {   Coef k = mkcoef_sc(s1, c1);
        #pragma unroll
        for (int n = 0; n < 8; n++) a[n] = v[n].y;
        r8B_apply(a, k);
        #pragma unroll
        for (int n = 0; n < 8; n++) v[n].y = a[n];
    }
    float s2 = fmaf(c1, ss, s1 * cc), c2 = fmaf(-s1, ss, c1 * cc);
    {   Coef k = mkcoef_sc(s2, c2);
        #pragma unroll
        for (int n = 0; n < 8; n++) a[n] = v[n].z;
        r8B_apply(a, k);
        #pragma unroll
        for (int n = 0; n < 8; n++) v[n].z = a[n];
    }
    float s3 = fmaf(c2, ss, s2 * cc), c3 = fmaf(-s2, ss, c2 * cc);
    {   Coef k = mkcoef_sc(s3, c3);
        #pragma unroll
        for (int n = 0; n < 8; n++) a[n] = v[n].w;
        r8B_apply(a, k);
        #pragma unroll
        for (int n = 0; n < 8; n++) v[n].w = a[n];
    }
}

template<int B>
__device__ __forceinline__ void r8B(float4* tile, int t, int R0){
    const int   mtop = (1 << (8 - B)) - 1;
    const int   base = ((t >> B) << (B + 3)) | (t & ((1 << B) - 1));
    const float sc   = PI / (float)(1 << (21 - B));
    const float cc   = 1.f - 0.5f * sc * sc;
    int   rl = (int)(__brev((unsigned)base) >> 21);
    int   jb = ((rl & mtop) << 11) + R0;
    float h0 = (float)jb * sc;
    int idx[8]; float4 v[8];
    #pragma unroll
    for (int n = 0; n < 8; n++){ idx[n] = swz(base + (n << B)); v[n] = tile[idx[n]]; }
    float s0 = sin_ap(h0), c0 = sin_ap(PIH - h0);
    r8B_regs_rot(v, s0, c0, sc, cc);
    #pragma unroll
    for (int n = 0; n < 8; n++) tile[idx[n]] = v[n];
}

// ================= Pass A: stages 1..11 =================
__global__ void __launch_bounds__(256) fftA(const float4* __restrict__ x4){
    __shared__ float4 tile[2048];
    const int t   = threadIdx.x;
    const int lb4 = blockIdx.x;
    const int w   = t >> 5, ln = t & 31;

    // fused load + closed-form stages (1,2)
    #pragma unroll
    for (int m = 0; m < 2; m++){
        int g = (w << 6) | ln | (m << 5);
        int b = g << 2;
        float4 e0 = x4[(((int)(__brev((unsigned)(b + 0)) >> 21)) << 9) + lb4];
        float4 e1 = x4[(((int)(__brev((unsigned)(b + 1)) >> 21)) << 9) + lb4];
        float4 e2 = x4[(((int)(__brev((unsigned)(b + 2)) >> 21)) << 9) + lb4];
        float4 e3 = x4[(((int)(__brev((unsigned)(b + 3)) >> 21)) << 9) + lb4];
        float4 w0, w1, w2;
#define G12(L) { \
        float A  = fabsf(e0.L + e1.L), Bv = fabsf(e2.L + e3.L); \
        float d1 = e0.L - e1.L,        d2 = e2.L - e3.L;        \
        float s  = A + Bv,             q  = A - Bv;             \
        w0.L = s * s; w2.L = q * q; w1.L = fmaf(d1, d1, d2 * d2); }
        G12(x) G12(y) G12(z) G12(w)
#undef G12
        tile[swz(b)] = w0; tile[swz(b + 1)] = w1; tile[swz(b + 2)] = w2; tile[swz(b + 3)] = w1;
    }
    __syncwarp();

    r8A<2>(tile, t); __syncwarp();      // stages 3,4,5 (warp-local rows)
    r8A<5>(tile, t); __syncthreads();   // stages 6,7,8

    // stages 9,10,11 (B=8) fused with direct transposed store to scratch.
    // Thread t holds rows t + 256n; scratch float addr for (row r, lane li):
    //   (r>>2)<<13 | (4*lb4+li)<<2 | (r&3)  =  base + (n<<19) + (li<<2)
    {
        const int   j0 = t & 255;
        const float h4 = (float)j0 * (PI / (float)(4 << 8));
        Coef k = mkcoef(h4);
        float4 v[8]; float a[8];
        #pragma unroll
        for (int n = 0; n < 8; n++) v[n] = tile[swz(t + (n << 8))];
        #pragma unroll
        for (int n = 0; n < 8; n++) a[n] = v[n].x;
        r8A_apply(a, k);
        #pragma unroll
        for (int n = 0; n < 8; n++){ v[n].x = a[n]; a[n] = v[n].y; }
        r8A_apply(a, k);
        #pragma unroll
        for (int n = 0; n < 8; n++){ v[n].y = a[n]; a[n] = v[n].z; }
        r8A_apply(a, k);
        #pragma unroll
        for (int n = 0; n < 8; n++){ v[n].z = a[n]; a[n] = v[n].w; }
        r8A_apply(a, k);
        #pragma unroll
        for (int n = 0; n < 8; n++) v[n].w = a[n];

        float* scrF = (float*)g_scr;
        const int base = ((t >> 2) << 13) + (lb4 << 4) + (t & 3);
        #pragma unroll
        for (int n = 0; n < 8; n++){
            float* d = scrF + base + (n << 19);
            d[0]  = v[n].x;
            d[4]  = v[n].y;
            d[8]  = v[n].z;
            d[12] = v[n].w;
        }
    }
}

// ================= Pass B: stages 12..22 + sqrt + bit-reversed store =================
__global__ void __launch_bounds__(256) fftB(float4* __restrict__ out4){
    __shared__ float4 tile[2048];
    const int t  = threadIdx.x;
    const int g  = blockIdx.x;
    const int R0 = g << 2;
    const int w  = t >> 5, ln = t & 31;

    // round 1 (stages 12,13,14): register-forwarded load (rows t + 256n)
    {
        const float sc = PI / (float)(1 << 13);
        const float cc = 1.f - 0.5f * sc * sc;
        float h0 = (float)R0 * sc;       // jb = R0
        float4 v[8];
        const float4* src = g_scr + ((long)g << 11) + t;
        #pragma unroll
        for (int n = 0; n < 8; n++) v[n] = src[n << 8];
        float s0 = sin_ap(h0), c0 = sin_ap(PIH - h0);
        r8B_regs_rot(v, s0, c0, sc, cc);
        #pragma unroll
        for (int n = 0; n < 8; n++) tile[swz(t + (n << 8))] = v[n];
    }
    __syncthreads();

    r8B<5>(tile, t, R0); __syncwarp();   // stages 15,16,17 (warp-local)
    r8B<2>(tile, t, R0); __syncwarp();   // stages 18,19,20 (warp-local)

    // final radix-4 (stages 21,22) + sqrt + bit-reversed scatter
    {
        const float hs = PI / (float)(1 << 21);
        #pragma unroll
        for (int m = 0; m < 2; m++){
            int gb   = (w << 6) | ln | (m << 5);
            int base = gb << 2;
            int i00 = swz(base), i01 = swz(base + 1), i10 = swz(base + 2), i11 = swz(base + 3);
            int rl = (int)(__brev((unsigned)base) >> 21);
            int jb = ((rl & 511) << 11) + R0;
            float h0 = (float)jb * hs;
            float4 v00 = tile[i00], v01 = tile[i01], v10 = tile[i10], v11 = tile[i11];
            float sh = sin_ap(h0), ch = sin_ap(PIH - h0);
#define RLF(L) { \
            float c2 = fmaf(-2.f * sh, sh, 1.f); float msh = -sh; \
            bfly(v00.L, v10.L, c2); bfly(v01.L, v11.L, c2); \
            bfly(v00.L, v01.L, ch); bfly(v10.L, v11.L, msh); }
#define ROT()  { float sn = fmaf(ch, hs, sh); ch = fmaf(-sh, hs, ch); sh = sn; }
            RLF(x) ROT()
            RLF(y) ROT()
            RLF(z) ROT()
            RLF(w)
#undef ROT
#undef RLF
#define SQ4(v) make_float4(sqrt_ap(fmaxf(v.x,0.f)), sqrt_ap(fmaxf(v.y,0.f)), \
                           sqrt_ap(fmaxf(v.z,0.f)), sqrt_ap(fmaxf(v.w,0.f)))
            out4[(((int)(__brev((unsigned)(base + 0)) >> 21)) << 9) + g] = SQ4(v00);
            out4[(((int)(__brev((unsigned)(base + 1)) >> 21)) << 9) + g] = SQ4(v01);
            out4[(((int)(__brev((unsigned)(base + 2)) >> 21)) << 9) + g] = SQ4(v10);
            out4[(((int)(__brev((unsigned)(base + 3)) >> 21)) << 9) + g] = SQ4(v11);
#undef SQ4
        }
    }
}

extern "C" void kernel_launch(void* const* d_in, const int* in_sizes, int n_in,
                              void* d_out, int out_size) {
    const float4* x4 = (const float4*)d_in[0];
    fftA<<<512, 256>>>(x4);
    fftB<<<512, 256>>>((float4*)d_out);
}